// round 12
// baseline (speedup 1.0000x reference)
#include <cuda_runtime.h>
#include <cuda_bf16.h>

// BayesianMF: per-user Bayesian linear update
//   prec_u = lambda_K + alpha * sum_{j in obs(u)} V_j V_j^T
//   rhs_u  = alpha * sum_j r_j V_j + lambda_K @ mu_K
//   mu_u   = prec_u^{-1} rhs_u ;  L_u = chol(prec_u^{-1}) ; out = mu + L z
//
// chol(P^{-1}) identity: J = reversal permutation, Q = J P J, H = chol(Q).
// Then L = J H^{-T} J = chol(P^{-1}), so L z = J H^{-T} (J z): one backward
// substitution, no explicit inverse, no second Cholesky.
//
// R12 = R11 with ONE change (accum inner loop):
//  - obs broadcast via uniform LDG (replaces 2 SHFL + tile staging)
//  - score carriers remapped to (lane&15) so score needs no SHFL
//  -> 4 SHFL + 2 LDG per observation (was 7 SHFL + staging).

#define D          16
#define NTRI       136          // 16*17/2
#define ACC_STRIDE 152          // 136 outer + 16 scoresum
#define MAX_USERS  50016
#define NNZ_MAX    1048576
#define ALPHA_F    2.0f
#define FULLM      0xffffffffu

#define TRI(i, j) (((i) * ((i) + 1)) / 2 + (j))

// Scratch (no cudaMalloc allowed). Zero-initialized at module load;
// scanC re-zeroes g_counts each run so graph replays stay correct.
__device__ __align__(16) float g_acc[(size_t)MAX_USERS * ACC_STRIDE];  // 30.4 MB
__device__ int  g_counts[MAX_USERS];
__device__ int  g_offsets[MAX_USERS + 1];
__device__ int  g_cursors[MAX_USERS];
__device__ int  g_blocksums[256];
__device__ int2 g_sorted[NNZ_MAX];                                     // 8 MB

// ---------------------------------------------------------------------------
// Phase 1a: histogram of user_ids (4 obs per thread, vector loads)
// ---------------------------------------------------------------------------
__global__ void hist_kernel(const int* __restrict__ user_ids, int nnz) {
    const int i4 = (blockIdx.x * blockDim.x + threadIdx.x) * 4;
    if (i4 + 3 < nnz) {
        const int4 u = *reinterpret_cast<const int4*>(user_ids + i4);
        atomicAdd(&g_counts[u.x], 1);
        atomicAdd(&g_counts[u.y], 1);
        atomicAdd(&g_counts[u.z], 1);
        atomicAdd(&g_counts[u.w], 1);
    } else {
        for (int i = i4; i < nnz; i++) atomicAdd(&g_counts[user_ids[i]], 1);
    }
}

// ---------------------------------------------------------------------------
// Phase 1b: parallel exclusive scan, 3 kernels.
// scanA: per-256-chunk sums.  scanB: 1-block scan of chunk sums (+sentinel).
// scanC: per-chunk prefix + write offsets/cursors + self-clean counts.
// ---------------------------------------------------------------------------
__global__ void scanA_kernel(int num_users) {
    __shared__ int sh[256];
    const int tid = threadIdx.x;
    const int i = blockIdx.x * 256 + tid;
    int v = (i < num_users) ? g_counts[i] : 0;
    sh[tid] = v;
    __syncthreads();
#pragma unroll
    for (int off = 128; off > 0; off >>= 1) {
        if (tid < off) sh[tid] += sh[tid + off];
        __syncthreads();
    }
    if (tid == 0) g_blocksums[blockIdx.x] = sh[0];
}

__global__ void scanB_kernel(int nblocks, int num_users) {
    __shared__ int sh[256];
    const int tid = threadIdx.x;
    int v = (tid < nblocks) ? g_blocksums[tid] : 0;
    sh[tid] = v;
    __syncthreads();
#pragma unroll
    for (int off = 1; off < 256; off <<= 1) {
        int val = (tid >= off) ? sh[tid - off] : 0;
        __syncthreads();
        sh[tid] += val;
        __syncthreads();
    }
    if (tid < nblocks) g_blocksums[tid] = sh[tid] - v;     // exclusive
    if (tid == nblocks - 1) g_offsets[num_users] = sh[tid]; // sentinel = nnz
}

__global__ void scanC_kernel(int num_users) {
    __shared__ int sh[256];
    const int tid = threadIdx.x;
    const int i = blockIdx.x * 256 + tid;
    int v = (i < num_users) ? g_counts[i] : 0;
    sh[tid] = v;
    __syncthreads();
#pragma unroll
    for (int off = 1; off < 256; off <<= 1) {
        int val = (tid >= off) ? sh[tid - off] : 0;
        __syncthreads();
        sh[tid] += val;
        __syncthreads();
    }
    if (i < num_users) {
        const int excl = sh[tid] - v + g_blocksums[blockIdx.x];
        g_offsets[i] = excl;
        g_cursors[i] = excl;
        g_counts[i] = 0;                  // self-clean for next replay
    }
}

// ---------------------------------------------------------------------------
// Phase 1c: bucket observations into CSR order (4 obs per thread)
// ---------------------------------------------------------------------------
__global__ void bucket_kernel(const int*   __restrict__ user_ids,
                              const int*   __restrict__ item_ids,
                              const float* __restrict__ ratings,
                              int nnz) {
    const int i4 = (blockIdx.x * blockDim.x + threadIdx.x) * 4;
    if (i4 + 3 < nnz) {
        const int4   u = *reinterpret_cast<const int4*>(user_ids + i4);
        const int4   it = *reinterpret_cast<const int4*>(item_ids + i4);
        const float4 r = *reinterpret_cast<const float4*>(ratings + i4);
        int p0 = atomicAdd(&g_cursors[u.x], 1);
        int p1 = atomicAdd(&g_cursors[u.y], 1);
        int p2 = atomicAdd(&g_cursors[u.z], 1);
        int p3 = atomicAdd(&g_cursors[u.w], 1);
        g_sorted[p0] = make_int2(it.x, __float_as_int(r.x));
        g_sorted[p1] = make_int2(it.y, __float_as_int(r.y));
        g_sorted[p2] = make_int2(it.z, __float_as_int(r.z));
        g_sorted[p3] = make_int2(it.w, __float_as_int(r.w));
    } else {
        for (int i = i4; i < nnz; i++) {
            int pos = atomicAdd(&g_cursors[user_ids[i]], 1);
            g_sorted[pos] = make_int2(item_ids[i], __float_as_int(ratings[i]));
        }
    }
}

// ---------------------------------------------------------------------------
// Phase 2: ONE WARP PER BLOCK accumulation.
// Clique decomposition of the 136-entry lower triangle:
//   lanes 0..3  ("TT"): two 2x2 triangles (6 entries)
//   lanes 4..31 ("Q") : one 2x2 block (4 entries)
//   lanes 4..19 carry score entry (lane & 15): uses own vl, no shuffle.
// Per obs: 1 uniform LDG (obs), 1 LDG (V row), 4 SHFL, 10 FMA.
// ---------------------------------------------------------------------------
__global__ void __launch_bounds__(32)
accum_kernel(const float* __restrict__ V, int num_users) {
    const int gw   = blockIdx.x;
    const int lane = threadIdx.x;
    if (gw >= num_users) return;

    const int start = __ldg(&g_offsets[gw]);
    const int n     = __ldg(&g_offsets[gw + 1]) - start;

    const bool isTT = (lane < 4);
    int s0, s1, s2, s3;          // shuffle source v-indices
    int d0, d1, d2, d3, d4, d5;  // destination offsets in acc row

    if (isTT) {
        const int t = lane;
        s0 = 4 * t; s1 = 4 * t + 1; s2 = 4 * t + 2; s3 = 4 * t + 3;
        d0 = TRI(4 * t,     4 * t);
        d1 = TRI(4 * t + 1, 4 * t);
        d2 = TRI(4 * t + 1, 4 * t + 1);
        d3 = TRI(4 * t + 2, 4 * t + 2);
        d4 = TRI(4 * t + 3, 4 * t + 2);
        d5 = TRI(4 * t + 3, 4 * t + 3);
    } else {
        const int c = lane - 4;
        int i0, k0;
        if (c < 4) {                      // diag block lower-left 2x2
            i0 = 4 * c + 2; k0 = 4 * c;
        } else {                          // off-diag block quadrant
            const int c2 = c - 4;
            const int m = c2 >> 2, q = c2 & 3;
            // (A,B) for m = 0..5: (0,1),(0,2),(0,3),(1,2),(1,3),(2,3)
            const int A = (m < 3) ? 0 : ((m < 5) ? 1 : 2);
            const int B = (m < 3) ? (m + 1) : ((m < 5) ? (m - 1) : 3);
            i0 = 4 * B + 2 * (q >> 1);
            k0 = 4 * A + 2 * (q & 1);
        }
        const int i1 = i0 + 1, k1 = k0 + 1;
        s0 = i0; s1 = i1; s2 = k0; s3 = k1;
        d0 = TRI(i0, k0); d1 = TRI(i0, k1);
        d2 = TRI(i1, k0); d3 = TRI(i1, k1);
        d4 = 0; d5 = 0;
    }
    // Score carriers: lanes 4..19 own score entry (lane & 15); they already
    // hold vl = v[lane & 15], so no shuffle is needed for the score product.
    const bool isScore = (lane >= 4 && lane < 20);

    float a0 = 0.f, a1 = 0.f, a2 = 0.f, a3 = 0.f, a4 = 0.f, a5 = 0.f;
    float asc = 0.f;

#pragma unroll 4
    for (int t = 0; t < n; t++) {
        const int2  ob = __ldg(&g_sorted[start + t]);   // uniform broadcast
        const float r  = __int_as_float(ob.y);
        const float vl = __ldg(&V[(ob.x << 4) + (lane & 15)]);
        const float w0 = __shfl_sync(FULLM, vl, s0);
        const float w1 = __shfl_sync(FULLM, vl, s1);
        const float w2 = __shfl_sync(FULLM, vl, s2);
        const float w3 = __shfl_sync(FULLM, vl, s3);
        if (isTT) {
            a0 += w0 * w0; a1 += w1 * w0; a2 += w1 * w1;
            a3 += w2 * w2; a4 += w3 * w2; a5 += w3 * w3;
        } else {
            a0 += w0 * w2; a1 += w0 * w3;
            a2 += w1 * w2; a3 += w1 * w3;
            asc += r * vl;   // only written back by score-carrier lanes
        }
    }

    float* acc = g_acc + (size_t)gw * ACC_STRIDE;
    if (isTT) {
        acc[d0] = a0; acc[d1] = a1; acc[d2] = a2;
        acc[d3] = a3; acc[d4] = a4; acc[d5] = a5;
    } else {
        acc[d0] = a0; acc[d1] = a1; acc[d2] = a2; acc[d3] = a3;
        if (isScore) acc[NTRI + (lane & 15)] = asc;
    }
}

// ---------------------------------------------------------------------------
// Phase 3: per-user dense solve (R5 verbatim; one thread per user)
// ---------------------------------------------------------------------------
__global__ void __launch_bounds__(128, 2)
solve_kernel(const float* __restrict__ lambdaK,
             const float* __restrict__ muK,
             const float* __restrict__ z,
             float*       __restrict__ out,
             int num_users) {
    int u = blockIdx.x * blockDim.x + threadIdx.x;
    if (u >= num_users) return;

    const float* S = g_acc + (size_t)u * ACC_STRIDE;

    // Q = J * prec * J, packed lower (i >= j)
    float H[NTRI];
#pragma unroll
    for (int i = 0; i < D; i++) {
#pragma unroll
        for (int j = 0; j <= i; j++) {
            const int a = 15 - i, b = 15 - j;   // b >= a
            H[TRI(i, j)] = __ldg(&lambdaK[a * D + b]) + ALPHA_F * S[TRI(b, a)];
        }
    }

    // Reversed rhs: w[i] = rhs[15-i]
    float w[D];
#pragma unroll
    for (int i = 0; i < D; i++) {
        const int a = 15 - i;
        float t = ALPHA_F * S[NTRI + a];
#pragma unroll
        for (int b = 0; b < D; b++) {
            t += __ldg(&lambdaK[a * D + b]) * __ldg(&muK[b]);
        }
        w[i] = t;
    }

    // In-place Cholesky of Q
    float dinv[D];
#pragma unroll
    for (int j = 0; j < D; j++) {
        float s = H[TRI(j, j)];
#pragma unroll
        for (int k = 0; k < j; k++) {
            const float g = H[TRI(j, k)];
            s -= g * g;
        }
        const float sq = sqrtf(s);
        const float rj = 1.0f / sq;
        H[TRI(j, j)] = sq;
        dinv[j] = rj;
#pragma unroll
        for (int i = j + 1; i < D; i++) {
            float t = H[TRI(i, j)];
#pragma unroll
            for (int k = 0; k < j; k++) {
                t -= H[TRI(i, k)] * H[TRI(j, k)];
            }
            H[TRI(i, j)] = t * rj;
        }
    }

    // Solve Q x = w: forward then backward, in place. mu[a] = w[15-a].
#pragma unroll
    for (int i = 0; i < D; i++) {
        float t = w[i];
#pragma unroll
        for (int k = 0; k < i; k++) t -= H[TRI(i, k)] * w[k];
        w[i] = t * dinv[i];
    }
#pragma unroll
    for (int i = D - 1; i >= 0; i--) {
        float t = w[i];
#pragma unroll
        for (int k = D - 1; k > i; k--) t -= H[TRI(k, i)] * w[k];
        w[i] = t * dinv[i];
    }

    // Sample term: L z = J H^{-T} (J z); one backward substitution.
    const float4* zr = reinterpret_cast<const float4*>(z + (size_t)u * D);
    float4 z0 = zr[0], z1 = zr[1], z2 = zr[2], z3 = zr[3];
    float zf[D] = {z0.x, z0.y, z0.z, z0.w, z1.x, z1.y, z1.z, z1.w,
                   z2.x, z2.y, z2.z, z2.w, z3.x, z3.y, z3.z, z3.w};
    float s[D];
#pragma unroll
    for (int i = 0; i < D; i++) s[i] = zf[15 - i];   // Jz
#pragma unroll
    for (int i = D - 1; i >= 0; i--) {
        float t = s[i];
#pragma unroll
        for (int k = D - 1; k > i; k--) t -= H[TRI(k, i)] * s[k];
        s[i] = t * dinv[i];
    }

    // out[a] = mu[a] + (Lz)[a] = w[15-a] + s[15-a]
    float4* o = reinterpret_cast<float4*>(out + (size_t)u * D);
    float r0[D];
#pragma unroll
    for (int a = 0; a < D; a++) r0[a] = w[15 - a] + s[15 - a];
    o[0] = make_float4(r0[0],  r0[1],  r0[2],  r0[3]);
    o[1] = make_float4(r0[4],  r0[5],  r0[6],  r0[7]);
    o[2] = make_float4(r0[8],  r0[9],  r0[10], r0[11]);
    o[3] = make_float4(r0[12], r0[13], r0[14], r0[15]);
}

// ---------------------------------------------------------------------------
extern "C" void kernel_launch(void* const* d_in, const int* in_sizes, int n_in,
                              void* d_out, int out_size) {
    const float* V       = (const float*)d_in[0];
    const float* ratings = (const float*)d_in[1];
    const float* muK     = (const float*)d_in[2];
    const float* lambdaK = (const float*)d_in[3];
    const float* z       = (const float*)d_in[4];
    const int*   uid     = (const int*)d_in[5];
    const int*   iid     = (const int*)d_in[6];

    const int nnz       = in_sizes[5];        // user_ids length
    const int num_users = in_sizes[4] / D;    // z is [U, 16]

    const int q = (nnz + 3) / 4;              // 4 obs per thread
    const int nchunks = (num_users + 255) / 256;  // 196 <= 256

    hist_kernel<<<(q + 255) / 256, 256>>>(uid, nnz);
    scanA_kernel<<<nchunks, 256>>>(num_users);
    scanB_kernel<<<1, 256>>>(nchunks, num_users);
    scanC_kernel<<<nchunks, 256>>>(num_users);
    bucket_kernel<<<(q + 255) / 256, 256>>>(uid, iid, ratings, nnz);

    accum_kernel<<<num_users, 32>>>(V, num_users);

    solve_kernel<<<(num_users + 127) / 128, 128>>>(lambdaK, muK, z,
                                                   (float*)d_out, num_users);
}

// round 13
// speedup vs baseline: 1.1093x; 1.1093x over previous
#include <cuda_runtime.h>
#include <cuda_bf16.h>

// BayesianMF: per-user Bayesian linear update
//   prec_u = lambda_K + alpha * sum_{j in obs(u)} V_j V_j^T
//   rhs_u  = alpha * sum_j r_j V_j + lambda_K @ mu_K
//   mu_u   = prec_u^{-1} rhs_u ;  L_u = chol(prec_u^{-1}) ; out = mu + L z
//
// chol(P^{-1}) identity: J = reversal permutation, Q = J P J, H = chol(Q).
// Then L = J H^{-T} J = chol(P^{-1}), so L z = J H^{-T} (J z): one backward
// substitution, no explicit inverse, no second Cholesky.
//
// R13 = R11 (best, 102.5us) + ONE change in solve_kernel:
//   g_acc row ingested via 38 LDG.128 into a per-thread buffer (spilled
//   buffer -> coalesced LDL) instead of ~152 strided scalar LDGs
//   (32 L1tex wavefronts EACH). ~3.5x fewer wavefronts on solve's
//   dominant stall source. All math byte-identical.

#define D          16
#define NTRI       136          // 16*17/2
#define ACC_STRIDE 152          // 136 outer + 16 scoresum
#define MAX_USERS  50016
#define NNZ_MAX    1048576
#define ALPHA_F    2.0f
#define FULLM      0xffffffffu

#define TRI(i, j) (((i) * ((i) + 1)) / 2 + (j))

// Scratch (no cudaMalloc allowed). Zero-initialized at module load;
// scanC re-zeroes g_counts each run so graph replays stay correct.
__device__ __align__(16) float g_acc[(size_t)MAX_USERS * ACC_STRIDE];  // 30.4 MB
__device__ int  g_counts[MAX_USERS];
__device__ int  g_offsets[MAX_USERS + 1];
__device__ int  g_cursors[MAX_USERS];
__device__ int  g_blocksums[256];
__device__ int2 g_sorted[NNZ_MAX];                                     // 8 MB

// ---------------------------------------------------------------------------
// Phase 1a: histogram of user_ids (4 obs per thread, vector loads)
// ---------------------------------------------------------------------------
__global__ void hist_kernel(const int* __restrict__ user_ids, int nnz) {
    const int i4 = (blockIdx.x * blockDim.x + threadIdx.x) * 4;
    if (i4 + 3 < nnz) {
        const int4 u = *reinterpret_cast<const int4*>(user_ids + i4);
        atomicAdd(&g_counts[u.x], 1);
        atomicAdd(&g_counts[u.y], 1);
        atomicAdd(&g_counts[u.z], 1);
        atomicAdd(&g_counts[u.w], 1);
    } else {
        for (int i = i4; i < nnz; i++) atomicAdd(&g_counts[user_ids[i]], 1);
    }
}

// ---------------------------------------------------------------------------
// Phase 1b: parallel exclusive scan, 3 kernels.
// ---------------------------------------------------------------------------
__global__ void scanA_kernel(int num_users) {
    __shared__ int sh[256];
    const int tid = threadIdx.x;
    const int i = blockIdx.x * 256 + tid;
    int v = (i < num_users) ? g_counts[i] : 0;
    sh[tid] = v;
    __syncthreads();
#pragma unroll
    for (int off = 128; off > 0; off >>= 1) {
        if (tid < off) sh[tid] += sh[tid + off];
        __syncthreads();
    }
    if (tid == 0) g_blocksums[blockIdx.x] = sh[0];
}

__global__ void scanB_kernel(int nblocks, int num_users) {
    __shared__ int sh[256];
    const int tid = threadIdx.x;
    int v = (tid < nblocks) ? g_blocksums[tid] : 0;
    sh[tid] = v;
    __syncthreads();
#pragma unroll
    for (int off = 1; off < 256; off <<= 1) {
        int val = (tid >= off) ? sh[tid - off] : 0;
        __syncthreads();
        sh[tid] += val;
        __syncthreads();
    }
    if (tid < nblocks) g_blocksums[tid] = sh[tid] - v;     // exclusive
    if (tid == nblocks - 1) g_offsets[num_users] = sh[tid]; // sentinel = nnz
}

__global__ void scanC_kernel(int num_users) {
    __shared__ int sh[256];
    const int tid = threadIdx.x;
    const int i = blockIdx.x * 256 + tid;
    int v = (i < num_users) ? g_counts[i] : 0;
    sh[tid] = v;
    __syncthreads();
#pragma unroll
    for (int off = 1; off < 256; off <<= 1) {
        int val = (tid >= off) ? sh[tid - off] : 0;
        __syncthreads();
        sh[tid] += val;
        __syncthreads();
    }
    if (i < num_users) {
        const int excl = sh[tid] - v + g_blocksums[blockIdx.x];
        g_offsets[i] = excl;
        g_cursors[i] = excl;
        g_counts[i] = 0;                  // self-clean for next replay
    }
}

// ---------------------------------------------------------------------------
// Phase 1c: bucket observations into CSR order (4 obs per thread)
// ---------------------------------------------------------------------------
__global__ void bucket_kernel(const int*   __restrict__ user_ids,
                              const int*   __restrict__ item_ids,
                              const float* __restrict__ ratings,
                              int nnz) {
    const int i4 = (blockIdx.x * blockDim.x + threadIdx.x) * 4;
    if (i4 + 3 < nnz) {
        const int4   u = *reinterpret_cast<const int4*>(user_ids + i4);
        const int4   it = *reinterpret_cast<const int4*>(item_ids + i4);
        const float4 r = *reinterpret_cast<const float4*>(ratings + i4);
        int p0 = atomicAdd(&g_cursors[u.x], 1);
        int p1 = atomicAdd(&g_cursors[u.y], 1);
        int p2 = atomicAdd(&g_cursors[u.z], 1);
        int p3 = atomicAdd(&g_cursors[u.w], 1);
        g_sorted[p0] = make_int2(it.x, __float_as_int(r.x));
        g_sorted[p1] = make_int2(it.y, __float_as_int(r.y));
        g_sorted[p2] = make_int2(it.z, __float_as_int(r.z));
        g_sorted[p3] = make_int2(it.w, __float_as_int(r.w));
    } else {
        for (int i = i4; i < nnz; i++) {
            int pos = atomicAdd(&g_cursors[user_ids[i]], 1);
            g_sorted[pos] = make_int2(item_ids[i], __float_as_int(ratings[i]));
        }
    }
}

// ---------------------------------------------------------------------------
// Phase 2: ONE WARP PER BLOCK accumulation (R11 verbatim — best measured).
// Clique decomposition of the 136-entry lower triangle:
//   lanes 0..3  ("TT"): two 2x2 triangles (6 entries)
//   lanes 4..31 ("Q") : one 2x2 block (4 entries)
//   lanes 4..19 additionally carry score entry d = lane-4.
// ---------------------------------------------------------------------------
__global__ void __launch_bounds__(32)
accum_kernel(const float* __restrict__ V, int num_users) {
    const int gw   = blockIdx.x;
    const int lane = threadIdx.x;
    if (gw >= num_users) return;

    const int start = __ldg(&g_offsets[gw]);
    const int n     = __ldg(&g_offsets[gw + 1]) - start;

    const bool isTT = (lane < 4);
    int s0, s1, s2, s3;          // shuffle source v-indices
    int d0, d1, d2, d3, d4, d5;  // destination offsets in acc row
    int   score_src  = 0;
    float score_mask = 0.f;
    int   score_dst  = 0;

    if (isTT) {
        const int t = lane;
        s0 = 4 * t; s1 = 4 * t + 1; s2 = 4 * t + 2; s3 = 4 * t + 3;
        d0 = TRI(4 * t,     4 * t);
        d1 = TRI(4 * t + 1, 4 * t);
        d2 = TRI(4 * t + 1, 4 * t + 1);
        d3 = TRI(4 * t + 2, 4 * t + 2);
        d4 = TRI(4 * t + 3, 4 * t + 2);
        d5 = TRI(4 * t + 3, 4 * t + 3);
    } else {
        const int c = lane - 4;
        int i0, k0;
        if (c < 4) {                      // diag block lower-left 2x2
            i0 = 4 * c + 2; k0 = 4 * c;
        } else {                          // off-diag block quadrant
            const int c2 = c - 4;
            const int m = c2 >> 2, q = c2 & 3;
            // (A,B) for m = 0..5: (0,1),(0,2),(0,3),(1,2),(1,3),(2,3)
            const int A = (m < 3) ? 0 : ((m < 5) ? 1 : 2);
            const int B = (m < 3) ? (m + 1) : ((m < 5) ? (m - 1) : 3);
            i0 = 4 * B + 2 * (q >> 1);
            k0 = 4 * A + 2 * (q & 1);
        }
        const int i1 = i0 + 1, k1 = k0 + 1;
        s0 = i0; s1 = i1; s2 = k0; s3 = k1;
        d0 = TRI(i0, k0); d1 = TRI(i0, k1);
        d2 = TRI(i1, k0); d3 = TRI(i1, k1);
        d4 = 0; d5 = 0;
        if (lane >= 4 && lane < 20) {     // score carrier
            score_src  = lane - 4;
            score_mask = 1.f;
            score_dst  = NTRI + (lane - 4);
        }
    }

    float a0 = 0.f, a1 = 0.f, a2 = 0.f, a3 = 0.f, a4 = 0.f, a5 = 0.f;
    float asc = 0.f;

    for (int t0 = 0; t0 < n; t0 += 32) {
        const int rem = n - t0;
        int2 ob = (lane < rem) ? __ldg(&g_sorted[start + t0 + lane])
                               : make_int2(0, 0);
        const int m = rem < 32 ? rem : 32;
        for (int t = 0; t < m; t++) {
            const int   it = __shfl_sync(FULLM, ob.x, t);
            const float r  = __shfl_sync(FULLM, __int_as_float(ob.y), t);
            const float vl = __ldg(&V[(it << 4) + (lane & 15)]);
            const float w0 = __shfl_sync(FULLM, vl, s0);
            const float w1 = __shfl_sync(FULLM, vl, s1);
            const float w2 = __shfl_sync(FULLM, vl, s2);
            const float w3 = __shfl_sync(FULLM, vl, s3);
            const float ws = __shfl_sync(FULLM, vl, score_src);
            if (isTT) {
                a0 += w0 * w0; a1 += w1 * w0; a2 += w1 * w1;
                a3 += w2 * w2; a4 += w3 * w2; a5 += w3 * w3;
            } else {
                a0 += w0 * w2; a1 += w0 * w3;
                a2 += w1 * w2; a3 += w1 * w3;
                asc += r * ws;  // only written back by score-carrier lanes
            }
        }
    }

    float* acc = g_acc + (size_t)gw * ACC_STRIDE;
    if (isTT) {
        acc[d0] = a0; acc[d1] = a1; acc[d2] = a2;
        acc[d3] = a3; acc[d4] = a4; acc[d5] = a5;
    } else {
        acc[d0] = a0; acc[d1] = a1; acc[d2] = a2; acc[d3] = a3;
        if (score_mask != 0.f) acc[score_dst] = asc;
    }
}

// ---------------------------------------------------------------------------
// Phase 3: per-user dense solve. R5 math; g_acc row ingested via 38 LDG.128
// into a per-thread buffer (spills -> coalesced LDL) instead of strided
// scalar LDGs (which cost 32 L1tex wavefronts each).
// ---------------------------------------------------------------------------
__global__ void __launch_bounds__(128, 2)
solve_kernel(const float* __restrict__ lambdaK,
             const float* __restrict__ muK,
             const float* __restrict__ z,
             float*       __restrict__ out,
             int num_users) {
    int u = blockIdx.x * blockDim.x + threadIdx.x;
    if (u >= num_users) return;

    // Vector ingest of this user's 608B accumulator row.
    float Sl[ACC_STRIDE];
    {
        const float4* S4 = reinterpret_cast<const float4*>(
            g_acc + (size_t)u * ACC_STRIDE);
        float4* B4 = reinterpret_cast<float4*>(Sl);
#pragma unroll
        for (int i = 0; i < ACC_STRIDE / 4; i++) B4[i] = __ldg(&S4[i]);
    }
    const float* S = Sl;

    // Q = J * prec * J, packed lower (i >= j)
    float H[NTRI];
#pragma unroll
    for (int i = 0; i < D; i++) {
#pragma unroll
        for (int j = 0; j <= i; j++) {
            const int a = 15 - i, b = 15 - j;   // b >= a
            H[TRI(i, j)] = __ldg(&lambdaK[a * D + b]) + ALPHA_F * S[TRI(b, a)];
        }
    }

    // Reversed rhs: w[i] = rhs[15-i]
    float w[D];
#pragma unroll
    for (int i = 0; i < D; i++) {
        const int a = 15 - i;
        float t = ALPHA_F * S[NTRI + a];
#pragma unroll
        for (int b = 0; b < D; b++) {
            t += __ldg(&lambdaK[a * D + b]) * __ldg(&muK[b]);
        }
        w[i] = t;
    }

    // In-place Cholesky of Q
    float dinv[D];
#pragma unroll
    for (int j = 0; j < D; j++) {
        float s = H[TRI(j, j)];
#pragma unroll
        for (int k = 0; k < j; k++) {
            const float g = H[TRI(j, k)];
            s -= g * g;
        }
        const float sq = sqrtf(s);
        const float rj = 1.0f / sq;
        H[TRI(j, j)] = sq;
        dinv[j] = rj;
#pragma unroll
        for (int i = j + 1; i < D; i++) {
            float t = H[TRI(i, j)];
#pragma unroll
            for (int k = 0; k < j; k++) {
                t -= H[TRI(i, k)] * H[TRI(j, k)];
            }
            H[TRI(i, j)] = t * rj;
        }
    }

    // Solve Q x = w: forward then backward, in place. mu[a] = w[15-a].
#pragma unroll
    for (int i = 0; i < D; i++) {
        float t = w[i];
#pragma unroll
        for (int k = 0; k < i; k++) t -= H[TRI(i, k)] * w[k];
        w[i] = t * dinv[i];
    }
#pragma unroll
    for (int i = D - 1; i >= 0; i--) {
        float t = w[i];
#pragma unroll
        for (int k = D - 1; k > i; k--) t -= H[TRI(k, i)] * w[k];
        w[i] = t * dinv[i];
    }

    // Sample term: L z = J H^{-T} (J z); one backward substitution.
    const float4* zr = reinterpret_cast<const float4*>(z + (size_t)u * D);
    float4 z0 = zr[0], z1 = zr[1], z2 = zr[2], z3 = zr[3];
    float zf[D] = {z0.x, z0.y, z0.z, z0.w, z1.x, z1.y, z1.z, z1.w,
                   z2.x, z2.y, z2.z, z2.w, z3.x, z3.y, z3.z, z3.w};
    float s[D];
#pragma unroll
    for (int i = 0; i < D; i++) s[i] = zf[15 - i];   // Jz
#pragma unroll
    for (int i = D - 1; i >= 0; i--) {
        float t = s[i];
#pragma unroll
        for (int k = D - 1; k > i; k--) t -= H[TRI(k, i)] * s[k];
        s[i] = t * dinv[i];
    }

    // out[a] = mu[a] + (Lz)[a] = w[15-a] + s[15-a]
    float4* o = reinterpret_cast<float4*>(out + (size_t)u * D);
    float r0[D];
#pragma unroll
    for (int a = 0; a < D; a++) r0[a] = w[15 - a] + s[15 - a];
    o[0] = make_float4(r0[0],  r0[1],  r0[2],  r0[3]);
    o[1] = make_float4(r0[4],  r0[5],  r0[6],  r0[7]);
    o[2] = make_float4(r0[8],  r0[9],  r0[10], r0[11]);
    o[3] = make_float4(r0[12], r0[13], r0[14], r0[15]);
}

// ---------------------------------------------------------------------------
extern "C" void kernel_launch(void* const* d_in, const int* in_sizes, int n_in,
                              void* d_out, int out_size) {
    const float* V       = (const float*)d_in[0];
    const float* ratings = (const float*)d_in[1];
    const float* muK     = (const float*)d_in[2];
    const float* lambdaK = (const float*)d_in[3];
    const float* z       = (const float*)d_in[4];
    const int*   uid     = (const int*)d_in[5];
    const int*   iid     = (const int*)d_in[6];

    const int nnz       = in_sizes[5];        // user_ids length
    const int num_users = in_sizes[4] / D;    // z is [U, 16]

    const int q = (nnz + 3) / 4;              // 4 obs per thread
    const int nchunks = (num_users + 255) / 256;  // 196 <= 256

    hist_kernel<<<(q + 255) / 256, 256>>>(uid, nnz);
    scanA_kernel<<<nchunks, 256>>>(num_users);
    scanB_kernel<<<1, 256>>>(nchunks, num_users);
    scanC_kernel<<<nchunks, 256>>>(num_users);
    bucket_kernel<<<(q + 255) / 256, 256>>>(uid, iid, ratings, nnz);

    accum_kernel<<<num_users, 32>>>(V, num_users);

    solve_kernel<<<(num_users + 127) / 128, 128>>>(lambdaK, muK, z,
                                                   (float*)d_out, num_users);
}